// round 1
// baseline (speedup 1.0000x reference)
#include <cuda_runtime.h>
#include <cuda_bf16.h>

// Problem constants
#define BB 4
#define CC 256
#define NN 4096      // H*W = 64*64
#define DD 32        // qk projection dim
#define MT 64        // query/key tile size

// Scratch (device globals: allocation-free rule)
__device__ float g_q[BB * DD * NN];    // [B][D][N]
__device__ float g_k[BB * DD * NN];    // [B][D][N]
__device__ float g_vt[BB * NN * CC];   // [B][N][C]  (v transposed: pixel-major)

// ---------------------------------------------------------------------------
// packed f32x2 helpers (sm_100+ PTX)
// ---------------------------------------------------------------------------
__device__ __forceinline__ void fma2(unsigned long long& d,
                                     unsigned long long a,
                                     unsigned long long b) {
    asm("fma.rn.f32x2 %0, %1, %2, %0;" : "+l"(d) : "l"(a), "l"(b));
}
__device__ __forceinline__ void mul2(unsigned long long& d,
                                     unsigned long long a) {
    asm("mul.rn.f32x2 %0, %0, %1;" : "+l"(d) : "l"(a));
}
__device__ __forceinline__ unsigned long long pack2(float x) {
    unsigned int u = __float_as_uint(x);
    return ((unsigned long long)u << 32) | (unsigned long long)u;
}

// ---------------------------------------------------------------------------
// P1: q/k projections.  grid = B * (N/64), block = 256
// q[b,d,i] = sum_c sem[b,c,i] * Wq[d,c] + bq[d]   (same for k from str)
// smem: inS[256][64] (64KB) + WS[32][256] (32KB) = 96KB
// ---------------------------------------------------------------------------
__global__ void __launch_bounds__(256, 2)
proj_qk_kernel(const float* __restrict__ sem, const float* __restrict__ str,
               const float* __restrict__ Wq, const float* __restrict__ bq,
               const float* __restrict__ Wk, const float* __restrict__ bk)
{
    extern __shared__ float sm1[];
    float* inS = sm1;            // 256*64
    float* WS  = sm1 + 256 * 64; // 32*256

    const int t   = threadIdx.x;
    const int b   = blockIdx.x >> 6;
    const int i0  = (blockIdx.x & 63) << 6;
    const int ii  = t & 63;
    const int grp = t >> 6;

    for (int pass = 0; pass < 2; ++pass) {
        const float* inp = pass ? str : sem;
        const float* Wp  = pass ? Wk  : Wq;
        const float* bp  = pass ? bk  : bq;
        float* outp      = pass ? g_k : g_q;

        // load input tile [256 c][64 px], coalesced
        #pragma unroll 4
        for (int i = 0; i < 64; ++i) {
            int idx = i * 256 + t;
            int c = idx >> 6, jj = idx & 63;
            inS[c * 64 + jj] = inp[(b * CC + c) * NN + i0 + jj];
        }
        // load weights [32][256]
        #pragma unroll 4
        for (int i = 0; i < 32; ++i)
            WS[i * 256 + t] = Wp[i * 256 + t];
        __syncthreads();

        float acc[8];
        #pragma unroll
        for (int k = 0; k < 8; ++k) acc[k] = bp[grp + 4 * k];

        for (int c = 0; c < 256; c += 4) {
            float x0 = inS[(c + 0) * 64 + ii];
            float x1 = inS[(c + 1) * 64 + ii];
            float x2 = inS[(c + 2) * 64 + ii];
            float x3 = inS[(c + 3) * 64 + ii];
            #pragma unroll
            for (int k = 0; k < 8; ++k) {
                int d = grp + 4 * k;
                float4 w = *(const float4*)&WS[d * 256 + c];
                acc[k] += x0 * w.x + x1 * w.y + x2 * w.z + x3 * w.w;
            }
        }
        #pragma unroll
        for (int k = 0; k < 8; ++k)
            outp[(b * DD + grp + 4 * k) * NN + i0 + ii] = acc[k];
        __syncthreads();
    }
}

// ---------------------------------------------------------------------------
// P2: v projection, output transposed to [B][N][C].  grid = B*(N/64), block 256
// v_t[b,j,c] = sum_cp str[b,cp,j] * Wv[c,cp] + bv[c]
// smem: strS[256][64] (64KB) + WT[256][65] transposed weight chunk (65KB)
// ---------------------------------------------------------------------------
__global__ void __launch_bounds__(256, 1)
proj_v_kernel(const float* __restrict__ str,
              const float* __restrict__ Wv, const float* __restrict__ bv)
{
    extern __shared__ float sm2[];
    float* strS = sm2;              // 256*64
    float* WT   = sm2 + 256 * 64;   // 256*65  (WT[cp][cc], pitch 65)

    const int t  = threadIdx.x;
    const int b  = blockIdx.x >> 6;
    const int j0 = (blockIdx.x & 63) << 6;

    #pragma unroll 4
    for (int i = 0; i < 64; ++i) {
        int idx = i * 256 + t;
        int cp = idx >> 6, jj = idx & 63;
        strS[cp * 64 + jj] = str[(b * CC + cp) * NN + j0 + jj];
    }

    const int cc  = t & 63;
    const int iib = (t >> 6) * 16;

    for (int chunk = 0; chunk < 4; ++chunk) {
        const int cb = chunk * 64;
        __syncthreads();  // protect WT (and first-iter strS) readers
        // WT[cp][i] = Wv[(cb+i)*256 + cp]; coalesced load, conflict-free store
        #pragma unroll 4
        for (int i = 0; i < 64; ++i)
            WT[t * 65 + i] = Wv[(cb + i) * 256 + t];
        __syncthreads();

        float acc[16];
        float bb = bv[cb + cc];
        #pragma unroll
        for (int k = 0; k < 16; ++k) acc[k] = bb;

        for (int cp = 0; cp < 256; ++cp) {
            float w = WT[cp * 65 + cc];
            const float4* s4 = (const float4*)&strS[cp * 64 + iib];
            float4 a0 = s4[0], a1 = s4[1], a2 = s4[2], a3 = s4[3];
            acc[0]  += a0.x * w;  acc[1]  += a0.y * w;
            acc[2]  += a0.z * w;  acc[3]  += a0.w * w;
            acc[4]  += a1.x * w;  acc[5]  += a1.y * w;
            acc[6]  += a1.z * w;  acc[7]  += a1.w * w;
            acc[8]  += a2.x * w;  acc[9]  += a2.y * w;
            acc[10] += a2.z * w;  acc[11] += a2.w * w;
            acc[12] += a3.x * w;  acc[13] += a3.y * w;
            acc[14] += a3.z * w;  acc[15] += a3.w * w;
        }
        #pragma unroll
        for (int k = 0; k < 16; ++k)
            g_vt[(b * NN + j0 + iib + k) * CC + cb + cc] = acc[k];
    }
}

// ---------------------------------------------------------------------------
// A: fused flash attention + epilogue.  grid = B*(N/64), block 256
// Thread (row = t%64, grp = t/64): S row `row`, O channels [grp*64, grp*64+64)
// smem: kT[64][36] + vS[64][256] + Ps[64][65] + red[256] + m/l/r[64 each]
// ---------------------------------------------------------------------------
__global__ void __launch_bounds__(256, 2)
attn_kernel(const float* __restrict__ sem, const float* __restrict__ gammaP,
            float* __restrict__ out)
{
    extern __shared__ float sm3[];
    float* kT  = sm3;                 // 64*36 = 2304
    float* vS  = kT + 2304;           // 64*256 = 16384
    float* Ps  = vS + 16384;          // 64*65 = 4160
    float* red = Ps + 4160;           // 256
    float* m_s = red + 256;           // 64
    float* l_s = m_s + 64;            // 64
    float* r_s = l_s + 64;            // 64

    const int t   = threadIdx.x;
    const int b   = blockIdx.x >> 6;
    const int i0  = (blockIdx.x & 63) << 6;
    const int row = t & 63;
    const int grp = t >> 6;

    // load this thread's query row into registers (coalesced per d)
    float qreg[32];
    #pragma unroll
    for (int d = 0; d < 32; ++d)
        qreg[d] = g_q[(b * DD + d) * NN + i0 + row];

    if (t < 64) { m_s[t] = -1e30f; l_s[t] = 0.f; }

    unsigned long long acc[32];
    #pragma unroll
    for (int m = 0; m < 32; ++m) acc[m] = 0ULL;
    __syncthreads();

    for (int kt = 0; kt < NN / MT; ++kt) {
        const int j0 = kt * MT;

        // --- load k tile transposed [jj][d] (pitch 36), coalesced global ---
        #pragma unroll
        for (int i = 0; i < 8; ++i) {
            int idx = i * 256 + t;
            int d = idx >> 6, jj = idx & 63;
            kT[jj * 36 + d] = g_k[(b * DD + d) * NN + j0 + jj];
        }
        // --- load v tile [j][c] as float4, fully coalesced ---
        {
            float4* vS4 = (float4*)vS;
            const float4* vg4 = (const float4*)g_vt;
            #pragma unroll
            for (int i = 0; i < 16; ++i) {
                int idx = i * 256 + t;
                int j = idx >> 6, c4 = idx & 63;
                vS4[j * 64 + c4] = vg4[(b * NN + j0 + j) * 64 + c4];
            }
        }
        __syncthreads();

        // --- S = q . k for this thread's 16 columns; track local max ---
        float lmax = -1e30f;
        #pragma unroll
        for (int u = 0; u < 16; ++u) {
            int jj = grp * 16 + u;
            const float4* kr = (const float4*)(kT + jj * 36);
            float s = 0.f;
            #pragma unroll
            for (int dv = 0; dv < 8; ++dv) {
                float4 kv = kr[dv];
                s += qreg[4 * dv + 0] * kv.x + qreg[4 * dv + 1] * kv.y
                   + qreg[4 * dv + 2] * kv.z + qreg[4 * dv + 3] * kv.w;
            }
            Ps[row * 65 + jj] = s;
            lmax = fmaxf(lmax, s);
        }
        red[grp * 64 + row] = lmax;
        __syncthreads();

        // --- row max / rescale factor (one thread per row) ---
        if (t < 64) {
            float mt = fmaxf(fmaxf(red[t], red[64 + t]),
                             fmaxf(red[128 + t], red[192 + t]));
            float mo = m_s[t];
            float mn = fmaxf(mo, mt);
            r_s[t] = __expf(mo - mn);
            m_s[t] = mn;
        }
        __syncthreads();

        // --- exponentiate in place, partial row sums, rescale accumulator ---
        {
            float mn = m_s[row];
            float lsum = 0.f;
            #pragma unroll
            for (int u = 0; u < 16; ++u) {
                int jj = grp * 16 + u;
                float p = __expf(Ps[row * 65 + jj] - mn);
                Ps[row * 65 + jj] = p;
                lsum += p;
            }
            red[grp * 64 + row] = lsum;
            unsigned long long r2 = pack2(r_s[row]);
            #pragma unroll
            for (int m = 0; m < 32; ++m) mul2(acc[m], r2);
        }
        __syncthreads();

        if (t < 64)
            l_s[t] = l_s[t] * r_s[t]
                   + red[t] + red[64 + t] + red[128 + t] + red[192 + t];

        // --- O update: acc[c] += P[row][j] * v[j][c]  (f32x2 packed) ---
        #pragma unroll 2
        for (int j = 0; j < 64; ++j) {
            unsigned long long p2 = pack2(Ps[row * 65 + j]);
            const ulonglong2* vv =
                (const ulonglong2*)(vS + j * 256 + grp * 64);
            #pragma unroll
            for (int c2 = 0; c2 < 16; ++c2) {
                ulonglong2 v = vv[c2];
                fma2(acc[2 * c2 + 0], p2, v.x);
                fma2(acc[2 * c2 + 1], p2, v.y);
            }
        }
        __syncthreads();  // protects kT/vS/red/l for next iteration
    }

    // --- epilogue: out = gamma * O / l + sem ---
    const float linv = 1.f / l_s[row];
    const float g = gammaP[0];
    const long base = (long)(b * CC + grp * 64) * NN + i0 + row;
    #pragma unroll
    for (int m = 0; m < 32; ++m) {
        unsigned long long a = acc[m];
        float lo = __uint_as_float((unsigned int)a);
        float hi = __uint_as_float((unsigned int)(a >> 32));
        long idx0 = base + (long)(2 * m) * NN;
        long idx1 = idx0 + NN;
        out[idx0] = g * (lo * linv) + sem[idx0];
        out[idx1] = g * (hi * linv) + sem[idx1];
    }
}

// ---------------------------------------------------------------------------
extern "C" void kernel_launch(void* const* d_in, const int* in_sizes, int n_in,
                              void* d_out, int out_size)
{
    const float* sem = (const float*)d_in[0];
    const float* str = (const float*)d_in[1];
    const float* Wq  = (const float*)d_in[2];
    const float* bq  = (const float*)d_in[3];
    const float* Wk  = (const float*)d_in[4];
    const float* bk  = (const float*)d_in[5];
    const float* Wv  = (const float*)d_in[6];
    const float* bv  = (const float*)d_in[7];
    const float* gam = (const float*)d_in[8];
    float* out = (float*)d_out;

    const int smem_p1 = (256 * 64 + 32 * 256) * 4;          // 98304
    const int smem_p2 = (256 * 64 + 256 * 65) * 4;          // 132096
    const int smem_at = (2304 + 16384 + 4160 + 256 + 192) * 4; // 93184

    cudaFuncSetAttribute(proj_qk_kernel,
        cudaFuncAttributeMaxDynamicSharedMemorySize, smem_p1);
    cudaFuncSetAttribute(proj_v_kernel,
        cudaFuncAttributeMaxDynamicSharedMemorySize, smem_p2);
    cudaFuncSetAttribute(attn_kernel,
        cudaFuncAttributeMaxDynamicSharedMemorySize, smem_at);

    dim3 grid(BB * (NN / MT));  // 256
    dim3 block(256);

    proj_qk_kernel<<<grid, block, smem_p1>>>(sem, str, Wq, bq, Wk, bk);
    proj_v_kernel<<<grid, block, smem_p2>>>(str, Wv, bv);
    attn_kernel<<<grid, block, smem_at>>>(sem, gam, out);
}

// round 3
// speedup vs baseline: 3.1606x; 3.1606x over previous
#include <cuda_runtime.h>
#include <cuda_bf16.h>
#include <cstdint>

#define BB 4
#define CC 256
#define NN 4096
#define DD 32
#define KT 64
#define NKT (NN / KT)

// Scratch
__device__ float g_qt[BB * NN * DD];   // [B][N][32]
__device__ float g_kt[BB * NN * DD];   // [B][N][32]
__device__ float g_vt[BB * NN * CC];   // [B][N][C]

// ---------------------------------------------------------------------------
__device__ __forceinline__ uint32_t f2tf32(float f) {
    uint32_t r;
    asm("cvt.rna.tf32.f32 %0, %1;" : "=r"(r) : "f"(f));
    return r;
}
__device__ __forceinline__ void mma8(float* d, const uint32_t* a,
                                     uint32_t b0, uint32_t b1) {
    asm("mma.sync.aligned.m16n8k8.row.col.f32.tf32.tf32.f32 "
        "{%0,%1,%2,%3},{%4,%5,%6,%7},{%8,%9},{%0,%1,%2,%3};"
        : "+f"(d[0]), "+f"(d[1]), "+f"(d[2]), "+f"(d[3])
        : "r"(a[0]), "r"(a[1]), "r"(a[2]), "r"(a[3]), "r"(b0), "r"(b1));
}

// ---------------------------------------------------------------------------
// P1: q/k projections -> [B][N][32]
// ---------------------------------------------------------------------------
__global__ void __launch_bounds__(256, 2)
proj_qk_kernel(const float* __restrict__ sem, const float* __restrict__ str,
               const float* __restrict__ Wq, const float* __restrict__ bq,
               const float* __restrict__ Wk, const float* __restrict__ bk)
{
    extern __shared__ float sm1[];
    float* inS = sm1;            // 256*64
    float* WS  = sm1 + 256 * 64; // 32*256

    const int t   = threadIdx.x;
    const int b   = blockIdx.x >> 6;
    const int i0  = (blockIdx.x & 63) << 6;
    const int ii  = t & 63;
    const int grp = t >> 6;

    for (int pass = 0; pass < 2; ++pass) {
        const float* inp = pass ? str : sem;
        const float* Wp  = pass ? Wk  : Wq;
        const float* bp  = pass ? bk  : bq;
        float* outp      = pass ? g_kt : g_qt;

        #pragma unroll 4
        for (int i = 0; i < 64; ++i) {
            int idx = i * 256 + t;
            int c = idx >> 6, jj = idx & 63;
            inS[c * 64 + jj] = inp[(b * CC + c) * NN + i0 + jj];
        }
        #pragma unroll 4
        for (int i = 0; i < 32; ++i)
            WS[i * 256 + t] = Wp[i * 256 + t];
        __syncthreads();

        float acc[8];
        #pragma unroll
        for (int k = 0; k < 8; ++k) acc[k] = bp[grp * 8 + k];

        for (int c = 0; c < 256; c += 4) {
            float x0 = inS[(c + 0) * 64 + ii];
            float x1 = inS[(c + 1) * 64 + ii];
            float x2 = inS[(c + 2) * 64 + ii];
            float x3 = inS[(c + 3) * 64 + ii];
            #pragma unroll
            for (int k = 0; k < 8; ++k) {
                float4 w = *(const float4*)&WS[(grp * 8 + k) * 256 + c];
                acc[k] += x0 * w.x + x1 * w.y + x2 * w.z + x3 * w.w;
            }
        }
        float* o = &outp[(size_t)(b * NN + i0 + ii) * DD + grp * 8];
        ((float4*)o)[0] = make_float4(acc[0], acc[1], acc[2], acc[3]);
        ((float4*)o)[1] = make_float4(acc[4], acc[5], acc[6], acc[7]);
        __syncthreads();
    }
}

// ---------------------------------------------------------------------------
// P2: v projection -> [B][N][C]  (validated in R1)
// ---------------------------------------------------------------------------
__global__ void __launch_bounds__(256, 1)
proj_v_kernel(const float* __restrict__ str,
              const float* __restrict__ Wv, const float* __restrict__ bv)
{
    extern __shared__ float sm2[];
    float* strS = sm2;              // 256*64
    float* WT   = sm2 + 256 * 64;   // 256*65

    const int t  = threadIdx.x;
    const int b  = blockIdx.x >> 6;
    const int j0 = (blockIdx.x & 63) << 6;

    #pragma unroll 4
    for (int i = 0; i < 64; ++i) {
        int idx = i * 256 + t;
        int cp = idx >> 6, jj = idx & 63;
        strS[cp * 64 + jj] = str[(b * CC + cp) * NN + j0 + jj];
    }

    const int cc  = t & 63;
    const int iib = (t >> 6) * 16;

    for (int chunk = 0; chunk < 4; ++chunk) {
        const int cb = chunk * 64;
        __syncthreads();
        #pragma unroll 4
        for (int i = 0; i < 64; ++i)
            WT[t * 65 + i] = Wv[(cb + i) * 256 + t];
        __syncthreads();

        float acc[16];
        float bb = bv[cb + cc];
        #pragma unroll
        for (int k = 0; k < 16; ++k) acc[k] = bb;

        for (int cp = 0; cp < 256; ++cp) {
            float w = WT[cp * 65 + cc];
            const float4* s4 = (const float4*)&strS[cp * 64 + iib];
            float4 a0 = s4[0], a1 = s4[1], a2 = s4[2], a3 = s4[3];
            acc[0]  += a0.x * w;  acc[1]  += a0.y * w;
            acc[2]  += a0.z * w;  acc[3]  += a0.w * w;
            acc[4]  += a1.x * w;  acc[5]  += a1.y * w;
            acc[6]  += a1.z * w;  acc[7]  += a1.w * w;
            acc[8]  += a2.x * w;  acc[9]  += a2.y * w;
            acc[10] += a2.z * w;  acc[11] += a2.w * w;
            acc[12] += a3.x * w;  acc[13] += a3.y * w;
            acc[14] += a3.z * w;  acc[15] += a3.w * w;
        }
        #pragma unroll
        for (int k = 0; k < 16; ++k)
            g_vt[(size_t)(b * NN + j0 + iib + k) * CC + cb + cc] = acc[k];
    }
}

// ---------------------------------------------------------------------------
// A: mma.sync tf32 flash attention (3xTF32 for S) + epilogue
// grid = B*(N/128)*2 = 256, block 256.
// CTA: 128 queries x 128 channels (half). 8 warps = 4m x 2n.
// ---------------------------------------------------------------------------
__global__ void __launch_bounds__(256, 1)
attn_mma_kernel(const float* __restrict__ sem, const float* __restrict__ gammaP,
                float* __restrict__ out)
{
    extern __shared__ float sm[];
    float* Qs  = sm;            // 128*36
    float* Khi = Qs + 4608;     // 2 bufs * 64*36
    float* Klo = Khi + 4608;
    float* Vs  = Klo + 4608;    // 2 bufs * 64*136
    float* Ps  = Vs + 17408;    // 128*68
    float* ls  = Ps + 8704;     // 2*128

    const int t    = threadIdx.x;
    const int lane = t & 31;
    const int wid  = t >> 5;
    const int wm   = wid & 3;
    const int wn   = wid >> 2;
    const int R0   = wm * 32;
    const int J0   = wn * 32;
    const int C0w  = wn * 64;

    const int bx  = blockIdx.x;
    const int b   = bx >> 6;
    const int i0  = ((bx >> 1) & 31) << 7;
    const int ch0 = (bx & 1) * 128;

    const int lq = lane >> 2;   // 0..7
    const int lr = lane & 3;    // 0..3

    // ---- Q staging: rows wid*16 .. +16, lane = d ----
    #pragma unroll
    for (int r = 0; r < 16; ++r) {
        int row = wid * 16 + r;
        Qs[row * 36 + lane] = g_qt[((size_t)b * NN + i0 + row) * DD + lane];
    }
    // ---- preload tile 0: K rows wid*8.., V rows wid*8.. ----
    {
        #pragma unroll
        for (int r = 0; r < 8; ++r) {
            int row = wid * 8 + r;
            float kv = g_kt[((size_t)b * NN + row) * DD + lane];
            uint32_t hb = f2tf32(kv);
            Khi[row * 36 + lane] = __uint_as_float(hb);
            Klo[row * 36 + lane] = kv - __uint_as_float(hb);
            float4 vv = *(const float4*)&g_vt[((size_t)b * NN + row) * CC + ch0 + lane * 4];
            *(float4*)&Vs[row * 136 + lane * 4] = vv;
        }
    }
    __syncthreads();

    float oacc[2][8][4];
    #pragma unroll
    for (int m = 0; m < 2; ++m)
        #pragma unroll
        for (int n = 0; n < 8; ++n)
            #pragma unroll
            for (int k = 0; k < 4; ++k) oacc[m][n][k] = 0.f;
    float lsum[4] = {0.f, 0.f, 0.f, 0.f};

    float4 vstage[8];
    float  kstage[8];

    for (int kt = 0; kt < NKT; ++kt) {
        const int buf = kt & 1;
        const float* Kh = Khi + buf * 2304;
        const float* Kl = Klo + buf * 2304;
        const float* Vb = Vs + buf * 8704;

        // stage next tile loads early (hide latency behind mma)
        if (kt + 1 < NKT) {
            const int j0n = (kt + 1) * KT;
            #pragma unroll
            for (int r = 0; r < 8; ++r) {
                int row = wid * 8 + r;
                kstage[r] = g_kt[((size_t)b * NN + j0n + row) * DD + lane];
                vstage[r] = *(const float4*)
                    &g_vt[((size_t)b * NN + j0n + row) * CC + ch0 + lane * 4];
            }
        }

        // ---- S = Q K^T (3xTF32), warp: 32x32 block ----
        float sacc[2][4][4];
        #pragma unroll
        for (int m = 0; m < 2; ++m)
            #pragma unroll
            for (int n = 0; n < 4; ++n)
                #pragma unroll
                for (int k = 0; k < 4; ++k) sacc[m][n][k] = 0.f;

        #pragma unroll
        for (int s = 0; s < 4; ++s) {
            uint32_t qh[2][4], ql[2][4];
            #pragma unroll
            for (int m = 0; m < 2; ++m) {
                int r = R0 + 16 * m + lq;
                int c = 8 * s + lr;
                float q0 = Qs[r * 36 + c];
                float q1 = Qs[(r + 8) * 36 + c];
                float q2 = Qs[r * 36 + c + 4];
                float q3 = Qs[(r + 8) * 36 + c + 4];
                qh[m][0] = f2tf32(q0); ql[m][0] = __float_as_uint(q0 - __uint_as_float(qh[m][0]));
                qh[m][1] = f2tf32(q1); ql[m][1] = __float_as_uint(q1 - __uint_as_float(qh[m][1]));
                qh[m][2] = f2tf32(q2); ql[m][2] = __float_as_uint(q2 - __uint_as_float(qh[m][2]));
                qh[m][3] = f2tf32(q3); ql[m][3] = __float_as_uint(q3 - __uint_as_float(qh[m][3]));
            }
            #pragma unroll
            for (int n = 0; n < 4; ++n) {
                int j = J0 + 8 * n + lq;
                int d = 8 * s + lr;
                uint32_t bh0 = __float_as_uint(Kh[j * 36 + d]);
                uint32_t bh1 = __float_as_uint(Kh[j * 36 + d + 4]);
                uint32_t bl0 = __float_as_uint(Kl[j * 36 + d]);
                uint32_t bl1 = __float_as_uint(Kl[j * 36 + d + 4]);
                mma8(sacc[0][n], qh[0], bh0, bh1);
                mma8(sacc[1][n], qh[1], bh0, bh1);
                mma8(sacc[0][n], ql[0], bh0, bh1);
                mma8(sacc[1][n], ql[1], bh0, bh1);
                mma8(sacc[0][n], qh[0], bl0, bl1);
                mma8(sacc[1][n], qh[1], bl0, bl1);
            }
        }

        // ---- exp, l partials, store P ----
        #pragma unroll
        for (int m = 0; m < 2; ++m) {
            int r = R0 + 16 * m + lq;
            #pragma unroll
            for (int n = 0; n < 4; ++n) {
                int jc = J0 + 8 * n + 2 * lr;
                float p0 = __expf(sacc[m][n][0]);
                float p1 = __expf(sacc[m][n][1]);
                float p2 = __expf(sacc[m][n][2]);
                float p3 = __expf(sacc[m][n][3]);
                lsum[2 * m]     += p0 + p1;
                lsum[2 * m + 1] += p2 + p3;
                *(float2*)&Ps[r * 68 + jc]       = make_float2(p0, p1);
                *(float2*)&Ps[(r + 8) * 68 + jc] = make_float2(p2, p3);
            }
        }
        __syncthreads();

        // ---- O += P V : warp 32 rows x 64 channels ----
        #pragma unroll
        for (int s = 0; s < 8; ++s) {
            uint32_t pa[2][4];
            #pragma unroll
            for (int m = 0; m < 2; ++m) {
                int r = R0 + 16 * m + lq;
                int c = 8 * s + lr;
                pa[m][0] = __float_as_uint(Ps[r * 68 + c]);
                pa[m][1] = __float_as_uint(Ps[(r + 8) * 68 + c]);
                pa[m][2] = __float_as_uint(Ps[r * 68 + c + 4]);
                pa[m][3] = __float_as_uint(Ps[(r + 8) * 68 + c + 4]);
            }
            #pragma unroll
            for (int n = 0; n < 8; ++n) {
                int j  = 8 * s + lr;
                int cc = C0w + 8 * n + lq;
                uint32_t vb0 = __float_as_uint(Vb[j * 136 + cc]);
                uint32_t vb1 = __float_as_uint(Vb[(j + 4) * 136 + cc]);
                mma8(oacc[0][n], pa[0], vb0, vb1);
                mma8(oacc[1][n], pa[1], vb0, vb1);
            }
        }

        // ---- store staged next tile into other buffer ----
        if (kt + 1 < NKT) {
            float* Khn = Khi + (buf ^ 1) * 2304;
            float* Kln = Klo + (buf ^ 1) * 2304;
            float* Vn  = Vs + (buf ^ 1) * 8704;
            #pragma unroll
            for (int r = 0; r < 8; ++r) {
                int row = wid * 8 + r;
                uint32_t hb = f2tf32(kstage[r]);
                Khn[row * 36 + lane] = __uint_as_float(hb);
                Kln[row * 36 + lane] = kstage[r] - __uint_as_float(hb);
                *(float4*)&Vn[row * 136 + lane * 4] = vstage[r];
            }
        }
        __syncthreads();
    }

    // ---- l reduction ----
    #pragma unroll
    for (int i = 0; i < 4; ++i) {
        lsum[i] += __shfl_xor_sync(0xFFFFFFFFu, lsum[i], 1);
        lsum[i] += __shfl_xor_sync(0xFFFFFFFFu, lsum[i], 2);
    }
    if (lr == 0) {
        #pragma unroll
        for (int i = 0; i < 4; ++i)
            ls[wn * 128 + R0 + lq + 8 * i] = lsum[i];
    }
    __syncthreads();

    float linv[4];
    #pragma unroll
    for (int i = 0; i < 4; ++i) {
        int r = R0 + lq + 8 * i;
        linv[i] = 1.f / (ls[r] + ls[128 + r]);
    }

    // ---- epilogue: out = gamma * O / l + sem ----
    const float g = gammaP[0];
    #pragma unroll
    for (int m = 0; m < 2; ++m) {
        #pragma unroll
        for (int n = 0; n < 8; ++n) {
            int ch = ch0 + C0w + 8 * n + 2 * lr;
            size_t ia = ((size_t)(b * CC + ch)) * NN + i0 + R0 + 16 * m + lq;
            out[ia]          = g * oacc[m][n][0] * linv[2 * m]     + sem[ia];
            out[ia + NN]     = g * oacc[m][n][1] * linv[2 * m]     + sem[ia + NN];
            out[ia + 8]      = g * oacc[m][n][2] * linv[2 * m + 1] + sem[ia + 8];
            out[ia + NN + 8] = g * oacc[m][n][3] * linv[2 * m + 1] + sem[ia + NN + 8];
        }
    }
}

// ---------------------------------------------------------------------------
extern "C" void kernel_launch(void* const* d_in, const int* in_sizes, int n_in,
                              void* d_out, int out_size)
{
    const float* sem = (const float*)d_in[0];
    const float* str = (const float*)d_in[1];
    const float* Wq  = (const float*)d_in[2];
    const float* bq  = (const float*)d_in[3];
    const float* Wk  = (const float*)d_in[4];
    const float* bk  = (const float*)d_in[5];
    const float* Wv  = (const float*)d_in[6];
    const float* bv  = (const float*)d_in[7];
    const float* gam = (const float*)d_in[8];
    float* out = (float*)d_out;

    const int smem_p1 = (256 * 64 + 32 * 256) * 4;   // 98304
    const int smem_p2 = (256 * 64 + 256 * 65) * 4;   // 132096
    const int smem_at = (4608 * 3 + 17408 + 8704 + 256) * 4; // 160768

    cudaFuncSetAttribute(proj_qk_kernel,
        cudaFuncAttributeMaxDynamicSharedMemorySize, smem_p1);
    cudaFuncSetAttribute(proj_v_kernel,
        cudaFuncAttributeMaxDynamicSharedMemorySize, smem_p2);
    cudaFuncSetAttribute(attn_mma_kernel,
        cudaFuncAttributeMaxDynamicSharedMemorySize, smem_at);

    proj_qk_kernel<<<BB * (NN / 64), 256, smem_p1>>>(sem, str, Wq, bq, Wk, bk);
    proj_v_kernel<<<BB * (NN / 64), 256, smem_p2>>>(str, Wv, bv);
    attn_mma_kernel<<<BB * (NN / 128) * 2, 256, smem_at>>>(sem, gam, out);
}

// round 5
// speedup vs baseline: 3.3620x; 1.0637x over previous
#include <cuda_runtime.h>
#include <cuda_bf16.h>
#include <cstdint>

#define BB 4
#define CC 256
#define NN 4096
#define DD 32
#define KT 64
#define NKT (NN / KT)

// Scratch
__device__ float g_qt[BB * NN * DD];   // [B][N][32]
__device__ float g_kt[BB * NN * DD];   // [B][N][32]
__device__ float g_vt[BB * NN * CC];   // [B][N][C]

// ---------------------------------------------------------------------------
__device__ __forceinline__ uint32_t f2tf32(float f) {
    uint32_t r;
    asm("cvt.rna.tf32.f32 %0, %1;" : "=r"(r) : "f"(f));
    return r;
}
__device__ __forceinline__ void mma8(float* d, const uint32_t* a,
                                     uint32_t b0, uint32_t b1) {
    asm("mma.sync.aligned.m16n8k8.row.col.f32.tf32.tf32.f32 "
        "{%0,%1,%2,%3},{%4,%5,%6,%7},{%8,%9},{%0,%1,%2,%3};"
        : "+f"(d[0]), "+f"(d[1]), "+f"(d[2]), "+f"(d[3])
        : "r"(a[0]), "r"(a[1]), "r"(a[2]), "r"(a[3]), "r"(b0), "r"(b1));
}
__device__ __forceinline__ uint32_t s2u(const void* p) {
    uint32_t a;
    asm("{ .reg .u64 t; cvta.to.shared.u64 t, %1; cvt.u32.u64 %0, t; }"
        : "=r"(a) : "l"(p));
    return a;
}
__device__ __forceinline__ void cp16(uint32_t dst, const void* src) {
    asm volatile("cp.async.cg.shared.global [%0], [%1], 16;"
                 :: "r"(dst), "l"(src) : "memory");
}
__device__ __forceinline__ void cp_commit() {
    asm volatile("cp.async.commit_group;" ::: "memory");
}
__device__ __forceinline__ void cp_wait0() {
    asm volatile("cp.async.wait_group 0;" ::: "memory");
}

// ---------------------------------------------------------------------------
// P1: q/k projections -> [B][N][32].  grid = B*(N/32) = 512, block 256, occ 3
// ---------------------------------------------------------------------------
__global__ void __launch_bounds__(256, 3)
proj_qk_kernel(const float* __restrict__ sem, const float* __restrict__ str,
               const float* __restrict__ Wq, const float* __restrict__ bq,
               const float* __restrict__ Wk, const float* __restrict__ bk)
{
    extern __shared__ float sm1[];
    float* inS = sm1;            // [256 c][32 px]  = 8192
    float* WT  = sm1 + 8192;     // [256 c][36 pad] = 9216 (d in first 32)

    const int t  = threadIdx.x;
    const int b  = blockIdx.x >> 7;
    const int i0 = (blockIdx.x & 127) << 5;
    const int px = t >> 3;
    const int dg = t & 7;

    for (int pass = 0; pass < 2; ++pass) {
        const float* inp = pass ? str : sem;
        const float* Wp  = pass ? Wk  : Wq;
        const float* bp  = pass ? bk  : bq;
        float* outp      = pass ? g_kt : g_qt;

        #pragma unroll 4
        for (int i = 0; i < 32; ++i) {
            int idx = i * 256 + t;
            int c = idx >> 5, p2 = idx & 31;
            inS[c * 32 + p2] = inp[(b * CC + c) * NN + i0 + p2];
        }
        #pragma unroll 4
        for (int i = 0; i < 32; ++i) {
            int idx = i * 256 + t;
            int d = idx >> 8, c = idx & 255;
            WT[c * 36 + d] = Wp[idx];
        }
        __syncthreads();

        float4 bb = *(const float4*)&bp[dg * 4];
        float a0 = bb.x, a1 = bb.y, a2 = bb.z, a3 = bb.w;

        #pragma unroll 4
        for (int c = 0; c < 256; ++c) {
            float x = inS[c * 32 + px];
            float4 w = *(const float4*)&WT[c * 36 + dg * 4];
            a0 += x * w.x; a1 += x * w.y; a2 += x * w.z; a3 += x * w.w;
        }
        *(float4*)&outp[(size_t)(b * NN + i0 + px) * DD + dg * 4] =
            make_float4(a0, a1, a2, a3);
        __syncthreads();
    }
}

// ---------------------------------------------------------------------------
// P2: v projection -> [B][N][C].  grid = B*(N/128)*(C/64) = 512, block 256
// ---------------------------------------------------------------------------
__global__ void __launch_bounds__(256, 3)
proj_v_kernel(const float* __restrict__ str,
              const float* __restrict__ Wv, const float* __restrict__ bv)
{
    extern __shared__ float sm2[];
    float* strS = sm2;           // [64 cp][128 px] = 8192
    float* WT   = sm2 + 8192;    // [64 cp][68 pad] = 4352

    const int t   = threadIdx.x;
    const int bx  = blockIdx.x;
    const int b   = bx >> 7;
    const int j0  = ((bx >> 2) & 31) << 7;
    const int cb  = (bx & 3) << 6;
    const int cc2 = (t & 31) * 2;
    const int pxg = (t >> 5) * 16;

    float acc[16][2];
    {
        float2 bb = *(const float2*)&bv[cb + cc2];
        #pragma unroll
        for (int k = 0; k < 16; ++k) { acc[k][0] = bb.x; acc[k][1] = bb.y; }
    }

    for (int chunk = 0; chunk < 4; ++chunk) {
        const int cp0 = chunk * 64;
        #pragma unroll 4
        for (int i = 0; i < 32; ++i) {
            int idx = i * 256 + t;
            int cp = idx >> 7, px = idx & 127;
            strS[cp * 128 + px] = str[(b * CC + cp0 + cp) * NN + j0 + px];
        }
        #pragma unroll 4
        for (int i = 0; i < 16; ++i) {
            int idx = i * 256 + t;
            int cc = idx >> 6, cp = idx & 63;
            WT[cp * 68 + cc] = Wv[(cb + cc) * CC + cp0 + cp];
        }
        __syncthreads();

        #pragma unroll 2
        for (int cp = 0; cp < 64; ++cp) {
            float2 w = *(const float2*)&WT[cp * 68 + cc2];
            const float4* s4 = (const float4*)&strS[cp * 128 + pxg];
            #pragma unroll
            for (int v = 0; v < 4; ++v) {
                float4 x = s4[v];
                acc[4 * v + 0][0] += x.x * w.x; acc[4 * v + 0][1] += x.x * w.y;
                acc[4 * v + 1][0] += x.y * w.x; acc[4 * v + 1][1] += x.y * w.y;
                acc[4 * v + 2][0] += x.z * w.x; acc[4 * v + 2][1] += x.z * w.y;
                acc[4 * v + 3][0] += x.w * w.x; acc[4 * v + 3][1] += x.w * w.y;
            }
        }
        __syncthreads();
    }
    #pragma unroll
    for (int k = 0; k < 16; ++k)
        *(float2*)&g_vt[(size_t)(b * NN + j0 + pxg + k) * CC + cb + cc2] =
            make_float2(acc[k][0], acc[k][1]);
}

// ---------------------------------------------------------------------------
// A: mma.sync tf32 flash attention (3xTF32 S, no-max softmax) + epilogue
// grid = B*(N/128)*2 = 256, block 256 (8 warps = 4m x 2n).
// ---------------------------------------------------------------------------
#define SQLO 0
#define SK   8192
#define SV   12800
#define SP   30208
#define SL   38912
#define VBUF 8704   // floats per V buffer (64 rows x 136)

__global__ void __launch_bounds__(256, 1)
attn_mma_kernel(const float* __restrict__ sem, const float* __restrict__ gammaP,
                float* __restrict__ out)
{
    extern __shared__ float sm[];
    float* Qlo = sm + SQLO;
    float* Kb  = sm + SK;
    float* Vb  = sm + SV;
    float* Ps  = sm + SP;
    float* ls  = sm + SL;
    const uint32_t smb = s2u(sm);

    const int t    = threadIdx.x;
    const int lane = t & 31;
    const int wid  = t >> 5;
    const int wm   = wid & 3;
    const int wn   = wid >> 2;
    const int R0   = wm * 32;
    const int J0   = wn * 32;
    const int C0w  = wn * 64;

    const int bx  = blockIdx.x;
    const int b   = bx >> 6;
    const int i0  = ((bx >> 1) & 31) << 7;
    const int ch0 = (bx & 1) * 128;

    const int lq = lane >> 2;
    const int lr = lane & 3;

    const float* kbase = &g_kt[(size_t)b * NN * DD];
    const float* vbase = &g_vt[(size_t)b * NN * CC + ch0];

    // ---- issue tile-0 K/V copies ----
    {
        uint32_t kdst = smb + SK * 4;
        #pragma unroll
        for (int i = 0; i < 2; ++i) {
            int idx = i * 256 + t;
            int row = idx >> 3, c2 = idx & 7;
            cp16(kdst + row * 144 + c2 * 16, kbase + row * DD + c2 * 4);
        }
        uint32_t vdst = smb + SV * 4;
        #pragma unroll
        for (int i = 0; i < 8; ++i) {
            int idx = i * 256 + t;
            int row = idx >> 5, c2 = idx & 31;
            cp16(vdst + row * 544 + c2 * 16, vbase + (size_t)row * CC + c2 * 4);
        }
        cp_commit();
    }

    // ---- Q fragments: hi in regs, lo in smem frag store ----
    uint32_t qh[4][2][4];
    #pragma unroll
    for (int s = 0; s < 4; ++s) {
        #pragma unroll
        for (int m = 0; m < 2; ++m) {
            int r = i0 + R0 + 16 * m + lq;
            int c = 8 * s + lr;
            const float* qb = &g_qt[((size_t)b * NN + r) * DD];
            float q0 = qb[c], q1 = qb[8 * DD + c];
            float q2 = qb[c + 4], q3 = qb[8 * DD + c + 4];
            qh[s][m][0] = f2tf32(q0); qh[s][m][1] = f2tf32(q1);
            qh[s][m][2] = f2tf32(q2); qh[s][m][3] = f2tf32(q3);
            int fb = (s * 8 + m * 4) * 256 + t;
            Qlo[fb]       = q0 - __uint_as_float(qh[s][m][0]);
            Qlo[fb + 256] = q1 - __uint_as_float(qh[s][m][1]);
            Qlo[fb + 512] = q2 - __uint_as_float(qh[s][m][2]);
            Qlo[fb + 768] = q3 - __uint_as_float(qh[s][m][3]);
        }
    }
    cp_wait0();
    __syncthreads();

    float oacc[2][8][4];
    #pragma unroll
    for (int m = 0; m < 2; ++m)
        #pragma unroll
        for (int n = 0; n < 8; ++n)
            #pragma unroll
            for (int k = 0; k < 4; ++k) oacc[m][n][k] = 0.f;
    float lsum[4] = {0.f, 0.f, 0.f, 0.f};

    for (int kt = 0; kt < NKT; ++kt) {
        const int buf = kt & 1;
        const float* Kr = Kb + buf * 2304;
        const float* Vr = Vb + buf * VBUF;

        // ---- issue next tile's copies into other buffer ----
        if (kt + 1 < NKT) {
            const int j0n = (kt + 1) * KT;
            uint32_t kdst = smb + (SK + (buf ^ 1) * 2304) * 4;
            #pragma unroll
            for (int i = 0; i < 2; ++i) {
                int idx = i * 256 + t;
                int row = idx >> 3, c2 = idx & 7;
                cp16(kdst + row * 144 + c2 * 16,
                     kbase + (size_t)(j0n + row) * DD + c2 * 4);
            }
            uint32_t vdst = smb + (SV + (buf ^ 1) * VBUF) * 4;
            #pragma unroll
            for (int i = 0; i < 8; ++i) {
                int idx = i * 256 + t;
                int row = idx >> 5, c2 = idx & 31;
                cp16(vdst + row * 544 + c2 * 16,
                     vbase + (size_t)(j0n + row) * CC + c2 * 4);
            }
            cp_commit();
        }

        // ---- S = Q K^T (3xTF32) ----
        float sacc[2][4][4];
        #pragma unroll
        for (int m = 0; m < 2; ++m)
            #pragma unroll
            for (int n = 0; n < 4; ++n)
                #pragma unroll
                for (int k = 0; k < 4; ++k) sacc[m][n][k] = 0.f;

        #pragma unroll
        for (int s = 0; s < 4; ++s) {
            uint32_t ql[2][4];
            #pragma unroll
            for (int m = 0; m < 2; ++m) {
                int fb = (s * 8 + m * 4) * 256 + t;
                ql[m][0] = __float_as_uint(Qlo[fb]);
                ql[m][1] = __float_as_uint(Qlo[fb + 256]);
                ql[m][2] = __float_as_uint(Qlo[fb + 512]);
                ql[m][3] = __float_as_uint(Qlo[fb + 768]);
            }
            #pragma unroll
            for (int n = 0; n < 4; ++n) {
                int j = J0 + 8 * n + lq;
                int d = 8 * s + lr;
                float k0 = Kr[j * 36 + d];
                float k1 = Kr[j * 36 + d + 4];
                uint32_t kh0 = f2tf32(k0), kh1 = f2tf32(k1);
                uint32_t kl0 = __float_as_uint(k0 - __uint_as_float(kh0));
                uint32_t kl1 = __float_as_uint(k1 - __uint_as_float(kh1));
                mma8(sacc[0][n], qh[s][0], kh0, kh1);
                mma8(sacc[1][n], qh[s][1], kh0, kh1);
                mma8(sacc[0][n], ql[0], kh0, kh1);
                mma8(sacc[1][n], ql[1], kh0, kh1);
                mma8(sacc[0][n], qh[s][0], kl0, kl1);
                mma8(sacc[1][n], qh[s][1], kl0, kl1);
            }
        }

        // ---- exp, l partials, store P ----
        #pragma unroll
        for (int m = 0; m < 2; ++m) {
            int r = R0 + 16 * m + lq;
            #pragma unroll
            for (int n = 0; n < 4; ++n) {
                int jc = J0 + 8 * n + 2 * lr;
                float p0 = __expf(sacc[m][n][0]);
                float p1 = __expf(sacc[m][n][1]);
                float p2 = __expf(sacc[m][n][2]);
                float p3 = __expf(sacc[m][n][3]);
                lsum[2 * m]     += p0 + p1;
                lsum[2 * m + 1] += p2 + p3;
                *(float2*)&Ps[r * 68 + jc]       = make_float2(p0, p1);
                *(float2*)&Ps[(r + 8) * 68 + jc] = make_float2(p2, p3);
            }
        }
        __syncthreads();

        // ---- O += P V ----
        #pragma unroll
        for (int s = 0; s < 8; ++s) {
            uint32_t pa[2][4];
            #pragma unroll
            for (int m = 0; m < 2; ++m) {
                int r = R0 + 16 * m + lq;
                int c = 8 * s + lr;
                pa[m][0] = __float_as_uint(Ps[r * 68 + c]);
                pa[m][1] = __float_as_uint(Ps[(r + 8) * 68 + c]);
                pa[m][2] = __float_as_uint(Ps[r * 68 + c + 4]);
                pa[m][3] = __float_as_uint(Ps[(r + 8) * 68 + c + 4]);
            }
            #pragma unroll
            for (int n = 0; n < 8; ++n) {
                int j  = 8 * s + lr;
                int cc = C0w + 8 * n + lq;
                uint32_t vb0 = __float_as_uint(Vr[j * 136 + cc]);
                uint32_t vb1 = __float_as_uint(Vr[(j + 4) * 136 + cc]);
                mma8(oacc[0][n], pa[0], vb0, vb1);
                mma8(oacc[1][n], pa[1], vb0, vb1);
            }
        }
        cp_wait0();
        __syncthreads();
    }

    // ---- l reduction ----
    #pragma unroll
    for (int i = 0; i < 4; ++i) {
        lsum[i] += __shfl_xor_sync(0xFFFFFFFFu, lsum[i], 1);
        lsum[i] += __shfl_xor_sync(0xFFFFFFFFu, lsum[i], 2);
    }
    if (lr == 0) {
        #pragma unroll
        for (int i = 0; i < 4; ++i)
            ls[wn * 128 + R0 + lq + 8 * i] = lsum[i];
    }
    __syncthreads();

    float linv[4];
    #pragma unroll
    for (int i = 0; i < 4; ++i) {
        int r = R0 + lq + 8 * i;
        linv[i] = 1.f / (ls[r] + ls[128 + r]);
    }

    // ---- epilogue ----
    const float g = gammaP[0];
    #pragma unroll
    for (int m = 0; m < 2; ++m) {
        #pragma unroll
        for (int n = 0; n < 8; ++n) {
            int ch = ch0 + C0w + 8 * n + 2 * lr;
            size_t ia = ((size_t)(b * CC + ch)) * NN + i0 + R0 + 16 * m + lq;
            out[ia]          = g * oacc[m][n][0] * linv[2 * m]     + sem[ia];
            out[ia + NN]     = g * oacc[m][n][1] * linv[2 * m]     + sem[ia + NN];
            out[ia + 8]      = g * oacc[m][n][2] * linv[2 * m + 1] + sem[ia + 8];
            out[ia + NN + 8] = g * oacc[m][n][3] * linv[2 * m + 1] + sem[ia + NN + 8];
        }
    }
}

// ---------------------------------------------------------------------------
extern "C" void kernel_launch(void* const* d_in, const int* in_sizes, int n_in,
                              void* d_out, int out_size)
{
    const float* sem = (const float*)d_in[0];
    const float* str = (const float*)d_in[1];
    const float* Wq  = (const float*)d_in[2];
    const float* bq  = (const float*)d_in[3];
    const float* Wk  = (const float*)d_in[4];
    const float* bk  = (const float*)d_in[5];
    const float* Wv  = (const float*)d_in[6];
    const float* bv  = (const float*)d_in[7];
    const float* gam = (const float*)d_in[8];
    float* out = (float*)d_out;

    const int smem_p1 = (8192 + 9216) * 4;         // 69632
    const int smem_p2 = (8192 + 4352) * 4;         // 50176
    const int smem_at = (39168) * 4;               // 156672

    cudaFuncSetAttribute(proj_qk_kernel,
        cudaFuncAttributeMaxDynamicSharedMemorySize, smem_p1);
    cudaFuncSetAttribute(proj_v_kernel,
        cudaFuncAttributeMaxDynamicSharedMemorySize, smem_p2);
    cudaFuncSetAttribute(attn_mma_kernel,
        cudaFuncAttributeMaxDynamicSharedMemorySize, smem_at);

    proj_qk_kernel<<<BB * (NN / 32), 256, smem_p1>>>(sem, str, Wq, bq, Wk, bk);
    proj_v_kernel<<<BB * (NN / 128) * 4, 256, smem_p2>>>(str, Wv, bv);
    attn_mma_kernel<<<BB * (NN / 128) * 2, 256, smem_at>>>(sem, gam, out);
}

// round 7
// speedup vs baseline: 5.2685x; 1.5671x over previous
#include <cuda_runtime.h>
#include <cuda_fp16.h>
#include <cstdint>

#define BB 4
#define CC 256
#define NN 4096
#define DD 32
#define KT 64
#define NKT (NN / KT)

// Scratch: pre-split half precision operands
__device__ __half g_qh[BB * NN * DD];
__device__ __half g_ql[BB * NN * DD];
__device__ __half g_kh[BB * NN * DD];
__device__ __half g_kl[BB * NN * DD];
__device__ __half g_vh[BB * CC * NN];   // [B][C][N]

// ---------------------------------------------------------------------------
__device__ __forceinline__ void mma16(float* d, const uint32_t* a,
                                      uint32_t b0, uint32_t b1) {
    asm("mma.sync.aligned.m16n8k16.row.col.f32.f16.f16.f32 "
        "{%0,%1,%2,%3},{%4,%5,%6,%7},{%8,%9},{%0,%1,%2,%3};"
        : "+f"(d[0]), "+f"(d[1]), "+f"(d[2]), "+f"(d[3])
        : "r"(a[0]), "r"(a[1]), "r"(a[2]), "r"(a[3]), "r"(b0), "r"(b1));
}
__device__ __forceinline__ uint32_t s2u(const void* p) {
    uint32_t a;
    asm("{ .reg .u64 t; cvta.to.shared.u64 t, %1; cvt.u32.u64 %0, t; }"
        : "=r"(a) : "l"(p));
    return a;
}
__device__ __forceinline__ void cp16(uint32_t dst, const void* src) {
    asm volatile("cp.async.cg.shared.global [%0], [%1], 16;"
                 :: "r"(dst), "l"(src) : "memory");
}
__device__ __forceinline__ void cp_commit() {
    asm volatile("cp.async.commit_group;" ::: "memory");
}
__device__ __forceinline__ void cp_wait0() {
    asm volatile("cp.async.wait_group 0;" ::: "memory");
}
__device__ __forceinline__ uint32_t pk2(float a, float b) {
    __half2 h = __floats2half2_rn(a, b);
    return *(uint32_t*)&h;
}

// ---------------------------------------------------------------------------
// P1: q/k projections -> hi/lo half [B][N][32].  grid = B*64, block 256
// ---------------------------------------------------------------------------
__global__ void __launch_bounds__(256, 2)
proj_qk_kernel(const float* __restrict__ sem, const float* __restrict__ str,
               const float* __restrict__ Wq, const float* __restrict__ bq,
               const float* __restrict__ Wk, const float* __restrict__ bk)
{
    extern __shared__ float sm1[];
    float* inS = sm1;            // 256*64
    float* WS  = sm1 + 256 * 64; // 32*256

    const int t   = threadIdx.x;
    const int b   = blockIdx.x >> 6;
    const int i0  = (blockIdx.x & 63) << 6;
    const int ii  = t & 63;
    const int grp = t >> 6;

    for (int pass = 0; pass < 2; ++pass) {
        const float* inp = pass ? str : sem;
        const float* Wp  = pass ? Wk  : Wq;
        const float* bp  = pass ? bk  : bq;
        __half* oh = pass ? g_kh : g_qh;
        __half* ol = pass ? g_kl : g_ql;

        #pragma unroll 4
        for (int i = 0; i < 64; ++i) {
            int idx = i * 256 + t;
            int c = idx >> 6, jj = idx & 63;
            inS[c * 64 + jj] = inp[(b * CC + c) * NN + i0 + jj];
        }
        #pragma unroll 4
        for (int i = 0; i < 32; ++i)
            WS[i * 256 + t] = Wp[i * 256 + t];
        __syncthreads();

        float acc[8];
        #pragma unroll
        for (int k = 0; k < 8; ++k) acc[k] = bp[grp * 8 + k];

        for (int c = 0; c < 256; c += 4) {
            float x0 = inS[(c + 0) * 64 + ii];
            float x1 = inS[(c + 1) * 64 + ii];
            float x2 = inS[(c + 2) * 64 + ii];
            float x3 = inS[(c + 3) * 64 + ii];
            #pragma unroll
            for (int k = 0; k < 8; ++k) {
                float4 w = *(const float4*)&WS[(grp * 8 + k) * 256 + c];
                acc[k] += x0 * w.x + x1 * w.y + x2 * w.z + x3 * w.w;
            }
        }
        float hi[8], lo[8];
        #pragma unroll
        for (int k = 0; k < 8; ++k) {
            __half h = __float2half_rn(acc[k]);
            hi[k] = __half2float(h);
            lo[k] = acc[k] - hi[k];
        }
        size_t base = ((size_t)(b * NN + i0 + ii)) * DD + grp * 8;
        uint4 HV = make_uint4(pk2(hi[0], hi[1]), pk2(hi[2], hi[3]),
                              pk2(hi[4], hi[5]), pk2(hi[6], hi[7]));
        uint4 LV = make_uint4(pk2(lo[0], lo[1]), pk2(lo[2], lo[3]),
                              pk2(lo[4], lo[5]), pk2(lo[6], lo[7]));
        *(uint4*)&oh[base] = HV;
        *(uint4*)&ol[base] = LV;
        __syncthreads();
    }
}

// ---------------------------------------------------------------------------
// P2: v projection -> half [B][C][N].  grid = 512, block 256
// ---------------------------------------------------------------------------
__global__ void __launch_bounds__(256, 3)
proj_v_kernel(const float* __restrict__ str,
              const float* __restrict__ Wv, const float* __restrict__ bv)
{
    extern __shared__ float sm2[];
    float* strS = sm2;           // [64 cp][128 px]
    float* WT   = sm2 + 8192;    // [64 cp][68 pad]

    const int t   = threadIdx.x;
    const int bx  = blockIdx.x;
    const int b   = bx >> 7;
    const int j0  = ((bx >> 2) & 31) << 7;
    const int cb  = (bx & 3) << 6;
    const int cc2 = (t & 31) * 2;
    const int pxg = (t >> 5) * 16;

    float acc[16][2];
    {
        float2 bb = *(const float2*)&bv[cb + cc2];
        #pragma unroll
        for (int k = 0; k < 16; ++k) { acc[k][0] = bb.x; acc[k][1] = bb.y; }
    }

    for (int chunk = 0; chunk < 4; ++chunk) {
        const int cp0 = chunk * 64;
        #pragma unroll 4
        for (int i = 0; i < 32; ++i) {
            int idx = i * 256 + t;
            int cp = idx >> 7, px = idx & 127;
            strS[cp * 128 + px] = str[(b * CC + cp0 + cp) * NN + j0 + px];
        }
        #pragma unroll 4
        for (int i = 0; i < 16; ++i) {
            int idx = i * 256 + t;
            int cc = idx >> 6, cp = idx & 63;
            WT[cp * 68 + cc] = Wv[(cb + cc) * CC + cp0 + cp];
        }
        __syncthreads();

        #pragma unroll 2
        for (int cp = 0; cp < 64; ++cp) {
            float2 w = *(const float2*)&WT[cp * 68 + cc2];
            const float4* s4 = (const float4*)&strS[cp * 128 + pxg];
            #pragma unroll
            for (int v = 0; v < 4; ++v) {
                float4 x = s4[v];
                acc[4 * v + 0][0] += x.x * w.x; acc[4 * v + 0][1] += x.x * w.y;
                acc[4 * v + 1][0] += x.y * w.x; acc[4 * v + 1][1] += x.y * w.y;
                acc[4 * v + 2][0] += x.z * w.x; acc[4 * v + 2][1] += x.z * w.y;
                acc[4 * v + 3][0] += x.w * w.x; acc[4 * v + 3][1] += x.w * w.y;
            }
        }
        __syncthreads();
    }
    #pragma unroll
    for (int e = 0; e < 2; ++e) {
        size_t base = ((size_t)(b * CC + cb + cc2 + e)) * NN + j0 + pxg;
        uint4 v0 = make_uint4(pk2(acc[0][e], acc[1][e]), pk2(acc[2][e], acc[3][e]),
                              pk2(acc[4][e], acc[5][e]), pk2(acc[6][e], acc[7][e]));
        uint4 v1 = make_uint4(pk2(acc[8][e], acc[9][e]), pk2(acc[10][e], acc[11][e]),
                              pk2(acc[12][e], acc[13][e]), pk2(acc[14][e], acc[15][e]));
        *(uint4*)&g_vh[base]     = v0;
        *(uint4*)&g_vh[base + 8] = v1;
    }
}

// ---------------------------------------------------------------------------
// A: fp16 mma flash attention with ONLINE SOFTMAX. 512 thr, 128q x 256ch. grid=128
// ---------------------------------------------------------------------------
#define SQH 0
#define SQL 10240
#define SKB 20480
#define SVB 40960
#define SPS 114688
#define SLS 131072      // shared: per-tile row-max reduction AND final l sums
#define SM_AT 133120

__device__ __forceinline__ void load_kv_tile(uint32_t smb, const __half* kh,
                                             const __half* kl, const __half* vh,
                                             int j0, int buf, int t)
{
    if (t < 256) {
        int row = t >> 2, seg = t & 3;
        cp16(smb + SKB + buf * 10240 + row * 80 + seg * 16,
             kh + (size_t)(j0 + row) * DD + seg * 8);
    } else {
        int t2 = t - 256;
        int row = t2 >> 2, seg = t2 & 3;
        cp16(smb + SKB + buf * 10240 + 5120 + row * 80 + seg * 16,
             kl + (size_t)(j0 + row) * DD + seg * 8);
    }
    #pragma unroll
    for (int i = 0; i < 4; ++i) {
        int idx = i * 512 + t;
        int c = idx >> 3, seg = idx & 7;
        cp16(smb + SVB + buf * 36864 + c * 144 + seg * 16,
             vh + (size_t)c * NN + j0 + seg * 8);
    }
}

__global__ void __launch_bounds__(512, 1)
attn_mma_kernel(const float* __restrict__ sem, const float* __restrict__ gammaP,
                float* __restrict__ out)
{
    extern __shared__ char smc[];
    const uint32_t smb = s2u(smc);
    float* red = (float*)(smc + SLS);   // 512 floats

    const int t    = threadIdx.x;
    const int lane = t & 31;
    const int wid  = t >> 5;
    const int wm   = wid & 3;
    const int wn   = wid >> 2;
    const int R0   = wm * 32;
    const int J0   = wn * 16;
    const int C0w  = wn * 64;
    const int lq   = lane >> 2;
    const int lr   = lane & 3;

    const int b  = blockIdx.x >> 5;
    const int i0 = (blockIdx.x & 31) << 7;

    const __half* khb = g_kh + (size_t)b * NN * DD;
    const __half* klb = g_kl + (size_t)b * NN * DD;
    const __half* vhb = g_vh + (size_t)b * CC * NN;

    #pragma unroll
    for (int i = 0; i < 2; ++i) {
        int idx = i * 512 + t;
        int row = (idx >> 2) & 127, seg = idx & 3;
        const __half* src = (idx < 512 ? g_qh : g_ql) +
                            ((size_t)(b * NN + i0 + row)) * DD + seg * 8;
        cp16(smb + (idx < 512 ? SQH : SQL) + row * 80 + seg * 16, src);
    }
    load_kv_tile(smb, khb, klb, vhb, 0, 0, t);
    cp_commit();
    cp_wait0();
    __syncthreads();

    float oacc[2][8][4];
    #pragma unroll
    for (int m = 0; m < 2; ++m)
        #pragma unroll
        for (int n = 0; n < 8; ++n)
            #pragma unroll
            for (int k = 0; k < 4; ++k) oacc[m][n][k] = 0.f;
    float lsum[4] = {0.f, 0.f, 0.f, 0.f};
    float mrun[4] = {-1e30f, -1e30f, -1e30f, -1e30f};

    for (int kt = 0; kt < NKT; ++kt) {
        const int buf = kt & 1;
        if (kt + 1 < NKT) {
            load_kv_tile(smb, khb, klb, vhb, (kt + 1) * KT, buf ^ 1, t);
            cp_commit();
        }

        // ---- S = Q K^T (3x fp16) ----
        const char* Kh = smc + SKB + buf * 10240;
        const char* Kl = Kh + 5120;
        float sacc[2][2][4];
        #pragma unroll
        for (int m = 0; m < 2; ++m)
            #pragma unroll
            for (int n = 0; n < 2; ++n)
                #pragma unroll
                for (int k = 0; k < 4; ++k) sacc[m][n][k] = 0.f;

        #pragma unroll
        for (int s = 0; s < 2; ++s) {
            uint32_t qh[2][4], ql[2][4];
            const int d = 16 * s + 2 * lr;
            #pragma unroll
            for (int m = 0; m < 2; ++m) {
                int r = R0 + 16 * m + lq;
                qh[m][0] = *(const uint32_t*)(smc + SQH + (r * 40 + d) * 2);
                qh[m][1] = *(const uint32_t*)(smc + SQH + ((r + 8) * 40 + d) * 2);
                qh[m][2] = *(const uint32_t*)(smc + SQH + (r * 40 + d + 8) * 2);
                qh[m][3] = *(const uint32_t*)(smc + SQH + ((r + 8) * 40 + d + 8) * 2);
                ql[m][0] = *(const uint32_t*)(smc + SQL + (r * 40 + d) * 2);
                ql[m][1] = *(const uint32_t*)(smc + SQL + ((r + 8) * 40 + d) * 2);
                ql[m][2] = *(const uint32_t*)(smc + SQL + (r * 40 + d + 8) * 2);
                ql[m][3] = *(const uint32_t*)(smc + SQL + ((r + 8) * 40 + d + 8) * 2);
            }
            #pragma unroll
            for (int n = 0; n < 2; ++n) {
                int j = J0 + 8 * n + lq;
                uint32_t kh0 = *(const uint32_t*)(Kh + (j * 40 + d) * 2);
                uint32_t kh1 = *(const uint32_t*)(Kh + (j * 40 + d + 8) * 2);
                uint32_t kl0 = *(const uint32_t*)(Kl + (j * 40 + d) * 2);
                uint32_t kl1 = *(const uint32_t*)(Kl + (j * 40 + d + 8) * 2);
                mma16(sacc[0][n], qh[0], kh0, kh1);
                mma16(sacc[1][n], qh[1], kh0, kh1);
                mma16(sacc[0][n], ql[0], kh0, kh1);
                mma16(sacc[1][n], ql[1], kh0, kh1);
                mma16(sacc[0][n], qh[0], kl0, kl1);
                mma16(sacc[1][n], qh[1], kl0, kl1);
            }
        }

        // ---- online max: strip max -> smem reduce -> running max ----
        float smax[4];
        #pragma unroll
        for (int m = 0; m < 2; ++m) {
            smax[2 * m] = fmaxf(fmaxf(sacc[m][0][0], sacc[m][0][1]),
                                fmaxf(sacc[m][1][0], sacc[m][1][1]));
            smax[2 * m + 1] = fmaxf(fmaxf(sacc[m][0][2], sacc[m][0][3]),
                                    fmaxf(sacc[m][1][2], sacc[m][1][3]));
        }
        #pragma unroll
        for (int i = 0; i < 4; ++i) {
            smax[i] = fmaxf(smax[i], __shfl_xor_sync(0xFFFFFFFFu, smax[i], 1));
            smax[i] = fmaxf(smax[i], __shfl_xor_sync(0xFFFFFFFFu, smax[i], 2));
        }
        if (lr == 0) {
            #pragma unroll
            for (int i = 0; i < 4; ++i)
                red[wn * 128 + R0 + 8 * i + lq] = smax[i];
        }
        __syncthreads();

        float f[4];
        #pragma unroll
        for (int i = 0; i < 4; ++i) {
            int r = R0 + 8 * i + lq;
            float mt = fmaxf(fmaxf(red[r], red[128 + r]),
                             fmaxf(red[256 + r], red[384 + r]));
            float mn = fmaxf(mrun[i], mt);
            f[i] = __expf(mrun[i] - mn);
            mrun[i] = mn;
            lsum[i] *= f[i];
        }
        if (f[0] < 1.f || f[1] < 1.f || f[2] < 1.f || f[3] < 1.f) {
            #pragma unroll
            for (int m = 0; m < 2; ++m)
                #pragma unroll
                for (int n = 0; n < 8; ++n) {
                    oacc[m][n][0] *= f[2 * m];
                    oacc[m][n][1] *= f[2 * m];
                    oacc[m][n][2] *= f[2 * m + 1];
                    oacc[m][n][3] *= f[2 * m + 1];
                }
        }

        // ---- exp(s - m), l partials, store P (half, swizzled) ----
        #pragma unroll
        for (int m = 0; m < 2; ++m) {
            int r = R0 + 16 * m + lq;
            #pragma unroll
            for (int n = 0; n < 2; ++n) {
                int jp = (J0 + 8 * n) / 2 + lr;
                float p0 = __expf(sacc[m][n][0] - mrun[2 * m]);
                float p1 = __expf(sacc[m][n][1] - mrun[2 * m]);
                float p2 = __expf(sacc[m][n][2] - mrun[2 * m + 1]);
                float p3 = __expf(sacc[m][n][3] - mrun[2 * m + 1]);
                lsum[2 * m]     += p0 + p1;
                lsum[2 * m + 1] += p2 + p3;
                *(uint32_t*)(smc + SPS + (r * 32 + (jp ^ (lq << 2))) * 4) = pk2(p0, p1);
                *(uint32_t*)(smc + SPS + ((r + 8) * 32 + (jp ^ (lq << 2))) * 4) = pk2(p2, p3);
            }
        }
        __syncthreads();

        // ---- O += P V ----
        const char* Vb = smc + SVB + buf * 36864;
        #pragma unroll
        for (int kk = 0; kk < 4; ++kk) {
            uint32_t pa[2][4];
            #pragma unroll
            for (int m = 0; m < 2; ++m) {
                int r = R0 + 16 * m + lq;
                int jp0 = 8 * kk + lr;
                int jp1 = jp0 + 4;
                pa[m][0] = *(const uint32_t*)(smc + SPS + (r * 32 + (jp0 ^ (lq << 2))) * 4);
                pa[m][1] = *(const uint32_t*)(smc + SPS + ((r + 8) * 32 + (jp0 ^ (lq << 2))) * 4);
                pa[m][2] = *(const uint32_t*)(smc + SPS + (r * 32 + (jp1 ^ (lq << 2))) * 4);
                pa[m][3] = *(const uint32_t*)(smc + SPS + ((r + 8) * 32 + (jp1 ^ (lq << 2))) * 4);
            }
            const int d = 16 * kk + 2 * lr;
            #pragma unroll
            for (int n = 0; n < 8; ++n) {
                int c = C0w + 8 * n + lq;
                uint32_t vb0 = *(const uint32_t*)(Vb + (c * 72 + d) * 2);
                uint32_t vb1 = *(const uint32_t*)(Vb + (c * 72 + d + 8) * 2);
                mma16(oacc[0][n], pa[0], vb0, vb1);
                mma16(oacc[1][n], pa[1], vb0, vb1);
            }
        }
        if (kt + 1 < NKT) cp_wait0();
        __syncthreads();
    }

    // ---- l reduction across lr, then across the 4 wn groups ----
    #pragma unroll
    for (int i = 0; i < 4; ++i) {
        lsum[i] += __shfl_xor_sync(0xFFFFFFFFu, lsum[i], 1);
        lsum[i] += __shfl_xor_sync(0xFFFFFFFFu, lsum[i], 2);
    }
    if (lr == 0) {
        #pragma unroll
        for (int i = 0; i < 4; ++i)
            red[wn * 128 + R0 + 8 * i + lq] = lsum[i];
    }
    __syncthreads();

    float linv[4];
    #pragma unroll
    for (int i = 0; i < 4; ++i) {
        int r = R0 + 8 * i + lq;
        linv[i] = 1.f / (red[r] + red[128 + r] + red[256 + r] + red[384 + r]);
    }

    // ---- epilogue: out = gamma * O / l + sem ----
    const float g = gammaP[0];
    #pragma unroll
    for (int m = 0; m < 2; ++m) {
        #pragma unroll
        for (int n = 0; n < 8; ++n) {
            int ch = C0w + 8 * n + 2 * lr;
            size_t ia = ((size_t)(b * CC + ch)) * NN + i0 + R0 + 16 * m + lq;
            out[ia]          = g * oacc[m][n][0] * linv[2 * m]     + sem[ia];
            out[ia + NN]     = g * oacc[m][n][1] * linv[2 * m]     + sem[ia + NN];
            out[ia + 8]      = g * oacc[m][n][2] * linv[2 * m + 1] + sem[ia + 8];
            out[ia + NN + 8] = g * oacc[m][n][3] * linv[2 * m + 1] + sem[ia + NN + 8];
        }
    }
}

// ---------------------------------------------------------------------------
extern "C" void kernel_launch(void* const* d_in, const int* in_sizes, int n_in,
                              void* d_out, int out_size)
{
    const float* sem = (const float*)d_in[0];
    const float* str = (const float*)d_in[1];
    const float* Wq  = (const float*)d_in[2];
    const float* bq  = (const float*)d_in[3];
    const float* Wk  = (const float*)d_in[4];
    const float* bk  = (const float*)d_in[5];
    const float* Wv  = (const float*)d_in[6];
    const float* bv  = (const float*)d_in[7];
    const float* gam = (const float*)d_in[8];
    float* out = (float*)d_out;

    const int smem_p1 = (256 * 64 + 32 * 256) * 4;  // 98304
    const int smem_p2 = (8192 + 4352) * 4;          // 50176
    const int smem_at = SM_AT;                      // 133120

    cudaFuncSetAttribute(proj_qk_kernel,
        cudaFuncAttributeMaxDynamicSharedMemorySize, smem_p1);
    cudaFuncSetAttribute(proj_v_kernel,
        cudaFuncAttributeMaxDynamicSharedMemorySize, smem_p2);
    cudaFuncSetAttribute(attn_mma_kernel,
        cudaFuncAttributeMaxDynamicSharedMemorySize, smem_at);

    proj_qk_kernel<<<BB * 64, 256, smem_p1>>>(sem, str, Wq, bq, Wk, bk);
    proj_v_kernel<<<BB * (NN / 128) * 4, 256, smem_p2>>>(str, Wv, bv);
    attn_mma_kernel<<<BB * (NN / 128), 512, smem_at>>>(sem, gam, out);
}

// round 8
// speedup vs baseline: 6.5474x; 1.2427x over previous
#include <cuda_runtime.h>
#include <cuda_fp16.h>
#include <cstdint>

#define BB 4
#define CC 256
#define NN 4096
#define DD 32
#define KT 64
#define NKT (NN / KT)

// Scratch: pre-split half precision operands (layouts unchanged from R7)
__device__ __half g_qh[BB * NN * DD];
__device__ __half g_ql[BB * NN * DD];
__device__ __half g_kh[BB * NN * DD];
__device__ __half g_kl[BB * NN * DD];
__device__ __half g_vh[BB * CC * NN];   // [B][C][N]

// ---------------------------------------------------------------------------
__device__ __forceinline__ void mma16(float* d, const uint32_t* a,
                                      uint32_t b0, uint32_t b1) {
    asm("mma.sync.aligned.m16n8k16.row.col.f32.f16.f16.f32 "
        "{%0,%1,%2,%3},{%4,%5,%6,%7},{%8,%9},{%0,%1,%2,%3};"
        : "+f"(d[0]), "+f"(d[1]), "+f"(d[2]), "+f"(d[3])
        : "r"(a[0]), "r"(a[1]), "r"(a[2]), "r"(a[3]), "r"(b0), "r"(b1));
}
__device__ __forceinline__ uint32_t s2u(const void* p) {
    uint32_t a;
    asm("{ .reg .u64 t; cvta.to.shared.u64 t, %1; cvt.u32.u64 %0, t; }"
        : "=r"(a) : "l"(p));
    return a;
}
__device__ __forceinline__ void cp16(uint32_t dst, const void* src) {
    asm volatile("cp.async.cg.shared.global [%0], [%1], 16;"
                 :: "r"(dst), "l"(src) : "memory");
}
__device__ __forceinline__ void cp_commit() {
    asm volatile("cp.async.commit_group;" ::: "memory");
}
__device__ __forceinline__ void cp_wait0() {
    asm volatile("cp.async.wait_group 0;" ::: "memory");
}
__device__ __forceinline__ uint32_t pk2(float a, float b) {
    __half2 h = __floats2half2_rn(a, b);
    return *(uint32_t*)&h;
}
__device__ __forceinline__ uint32_t pk2h(__half a, __half b) {
    __half2 h = __halves2half2(a, b);
    return *(uint32_t*)&h;
}

// ===========================================================================
// P1: q/k projections via fp16 MMA (3-term hi/lo). grid = B*32 = 128, blk 256
//   q[px][d] = sum_cp in[px][cp] * W[d][cp]   (A=in, B=W, C=[px][d])
// smem u32: INH [32pair][136] | INL | WH [32d][132] | WL
// ===========================================================================
#define P1_INH 0
#define P1_INL 4352
#define P1_WH  8704
#define P1_WL  12928
#define P1_TOT 17152   // u32 -> 68608 B

__global__ void __launch_bounds__(256, 2)
proj_qk_mma(const float* __restrict__ sem, const float* __restrict__ str,
            const float* __restrict__ Wq, const float* __restrict__ bq,
            const float* __restrict__ Wk, const float* __restrict__ bk)
{
    extern __shared__ uint32_t smq[];
    uint32_t* INH = smq + P1_INH;
    uint32_t* INL = smq + P1_INL;
    uint32_t* WH  = smq + P1_WH;
    uint32_t* WL  = smq + P1_WL;

    const int t    = threadIdx.x;
    const int lane = t & 31;
    const int wid  = t >> 5;
    const int wm   = wid & 3;          // px group (x32)
    const int wn   = wid >> 2;         // d group (x16)
    const int lq   = lane >> 2;
    const int lr   = lane & 3;

    const int b   = blockIdx.x >> 5;
    const int px0 = (blockIdx.x & 31) << 7;

    for (int pass = 0; pass < 2; ++pass) {
        const float* inp = pass ? str : sem;
        const float* Wp  = pass ? Wk  : Wq;
        const float* bp  = pass ? bk  : bq;
        uint32_t* oh = (uint32_t*)(pass ? g_kh : g_qh);
        uint32_t* ol = (uint32_t*)(pass ? g_kl : g_ql);

        // stage W [32d][128 cp-pairs] hi/lo
        #pragma unroll
        for (int it = 0; it < 16; ++it) {
            int idx = it * 256 + t;
            int d = idx >> 7, pr = idx & 127;
            float2 w = *(const float2*)&Wp[d * CC + 2 * pr];
            __half h0 = __float2half_rn(w.x), h1 = __float2half_rn(w.y);
            WH[d * 132 + pr] = pk2h(h0, h1);
            WL[d * 132 + pr] = pk2(w.x - __half2float(h0), w.y - __half2float(h1));
        }

        float cq[2][2][4];
        #pragma unroll
        for (int mm = 0; mm < 2; ++mm)
            #pragma unroll
            for (int n = 0; n < 2; ++n)
                #pragma unroll
                for (int k = 0; k < 4; ++k) cq[mm][n][k] = 0.f;

        for (int chunk = 0; chunk < 4; ++chunk) {
            __syncthreads();   // W ready (ch0) / prev MMA done before restage
            // stage input chunk [32 cp-pairs][128px] hi/lo
            #pragma unroll
            for (int it = 0; it < 16; ++it) {
                int idx = it * 256 + t;
                int i = idx >> 7, px = idx & 127;
                size_t g = (size_t)(b * CC + chunk * 64 + 2 * i) * NN + px0 + px;
                float x0 = inp[g], x1 = inp[g + NN];
                __half h0 = __float2half_rn(x0), h1 = __float2half_rn(x1);
                INH[i * 136 + px] = pk2h(h0, h1);
                INL[i * 136 + px] = pk2(x0 - __half2float(h0), x1 - __half2float(h1));
            }
            __syncthreads();

            #pragma unroll
            for (int s = 0; s < 4; ++s) {
                uint32_t ah[2][4], al[2][4];
                const int ro  = (8 * s + lr) * 136;
                const int ro4 = (8 * s + lr + 4) * 136;
                #pragma unroll
                for (int mm = 0; mm < 2; ++mm) {
                    int pxm = wm * 32 + mm * 16 + lq;
                    ah[mm][0] = INH[ro + pxm];  ah[mm][1] = INH[ro + pxm + 8];
                    ah[mm][2] = INH[ro4 + pxm]; ah[mm][3] = INH[ro4 + pxm + 8];
                    al[mm][0] = INL[ro + pxm];  al[mm][1] = INL[ro + pxm + 8];
                    al[mm][2] = INL[ro4 + pxm]; al[mm][3] = INL[ro4 + pxm + 8];
                }
                #pragma unroll
                for (int n = 0; n < 2; ++n) {
                    int drow = ((wn * 2 + n) * 8 + lq) * 132 + chunk * 32;
                    uint32_t bh0 = WH[drow + 8 * s + lr];
                    uint32_t bh1 = WH[drow + 8 * s + lr + 4];
                    uint32_t bl0 = WL[drow + 8 * s + lr];
                    uint32_t bl1 = WL[drow + 8 * s + lr + 4];
                    #pragma unroll
                    for (int mm = 0; mm < 2; ++mm) {
                        mma16(cq[mm][n], ah[mm], bh0, bh1);
                        mma16(cq[mm][n], al[mm], bh0, bh1);
                        mma16(cq[mm][n], ah[mm], bl0, bl1);
                    }
                }
            }
        }
        __syncthreads();   // MMA done before next pass restages

        // epilogue: +bias, hi/lo split, store [px][d] packed
        #pragma unroll
        for (int mm = 0; mm < 2; ++mm) {
            #pragma unroll
            for (int n = 0; n < 2; ++n) {
                int pxr = px0 + wm * 32 + mm * 16 + lq;
                int d0  = (wn * 2 + n) * 8 + 2 * lr;
                float b0 = __ldg(&bp[d0]), b1 = __ldg(&bp[d0 + 1]);
                float q0 = cq[mm][n][0] + b0, q1 = cq[mm][n][1] + b1;
                float q2 = cq[mm][n][2] + b0, q3 = cq[mm][n][3] + b1;
                __half h0 = __float2half_rn(q0), h1 = __float2half_rn(q1);
                __half h2 = __float2half_rn(q2), h3 = __float2half_rn(q3);
                size_t i0w = (size_t)(b * NN + pxr) * 16 + (wn * 2 + n) * 4 + lr;
                oh[i0w]       = pk2h(h0, h1);
                ol[i0w]       = pk2(q0 - __half2float(h0), q1 - __half2float(h1));
                oh[i0w + 128] = pk2h(h2, h3);
                ol[i0w + 128] = pk2(q2 - __half2float(h2), q3 - __half2float(h3));
            }
        }
    }
}

// ===========================================================================
// P2: v projection via fp16 MMA -> vT [C][N] directly. grid = 128, blk 256
//   vT[cc][px] = sum_cp W[cc][cp] * in[px][cp]   (A=W, B=in, C=[cc][px])
// smem u32: INH [32pair][136] | INL | WH [256cc][36] | WL
// ===========================================================================
#define P2_INH 0
#define P2_INL 4352
#define P2_WH  8704
#define P2_WL  17920
#define P2_TOT 27136   // u32 -> 108544 B

__global__ void __launch_bounds__(256, 1)
proj_v_mma(const float* __restrict__ str,
           const float* __restrict__ Wv, const float* __restrict__ bv)
{
    extern __shared__ uint32_t smv[];
    uint32_t* INH = smv + P2_INH;
    uint32_t* INL = smv + P2_INL;
    uint32_t* WH  = smv + P2_WH;
    uint32_t* WL  = smv + P2_WL;

    const int t    = threadIdx.x;
    const int lane = t & 31;
    const int wid  = t >> 5;
    const int m0   = wid * 32;        // cc group
    const int lq   = lane >> 2;
    const int lr   = lane & 3;

    const int b   = blockIdx.x >> 5;
    const int px0 = (blockIdx.x & 31) << 7;

    float cv[2][16][4];
    #pragma unroll
    for (int mm = 0; mm < 2; ++mm)
        #pragma unroll
        for (int n = 0; n < 16; ++n)
            #pragma unroll
            for (int k = 0; k < 4; ++k) cv[mm][n][k] = 0.f;

    for (int chunk = 0; chunk < 4; ++chunk) {
        if (chunk) __syncthreads();   // prev MMA done before restage
        // stage input chunk [32 cp-pairs][128px]
        #pragma unroll
        for (int it = 0; it < 16; ++it) {
            int idx = it * 256 + t;
            int i = idx >> 7, px = idx & 127;
            size_t g = (size_t)(b * CC + chunk * 64 + 2 * i) * NN + px0 + px;
            float x0 = str[g], x1 = str[g + NN];
            __half h0 = __float2half_rn(x0), h1 = __float2half_rn(x1);
            INH[i * 136 + px] = pk2h(h0, h1);
            INL[i * 136 + px] = pk2(x0 - __half2float(h0), x1 - __half2float(h1));
        }
        // stage W chunk [256cc][32 cp-pairs]
        #pragma unroll
        for (int it = 0; it < 32; ++it) {
            int idx = it * 256 + t;
            int cc = idx >> 5, pr = idx & 31;
            float2 w = *(const float2*)&Wv[(size_t)cc * CC + chunk * 64 + 2 * pr];
            __half h0 = __float2half_rn(w.x), h1 = __float2half_rn(w.y);
            WH[cc * 36 + pr] = pk2h(h0, h1);
            WL[cc * 36 + pr] = pk2(w.x - __half2float(h0), w.y - __half2float(h1));
        }
        __syncthreads();

        #pragma unroll
        for (int s = 0; s < 4; ++s) {
            uint32_t ah[2][4], al[2][4];
            #pragma unroll
            for (int mm = 0; mm < 2; ++mm) {
                int r0 = m0 + mm * 16;
                ah[mm][0] = WH[(r0 + lq) * 36 + 8 * s + lr];
                ah[mm][1] = WH[(r0 + lq + 8) * 36 + 8 * s + lr];
                ah[mm][2] = WH[(r0 + lq) * 36 + 8 * s + lr + 4];
                ah[mm][3] = WH[(r0 + lq + 8) * 36 + 8 * s + lr + 4];
                al[mm][0] = WL[(r0 + lq) * 36 + 8 * s + lr];
                al[mm][1] = WL[(r0 + lq + 8) * 36 + 8 * s + lr];
                al[mm][2] = WL[(r0 + lq) * 36 + 8 * s + lr + 4];
                al[mm][3] = WL[(r0 + lq + 8) * 36 + 8 * s + lr + 4];
            }
            const int ro  = (8 * s + lr) * 136;
            const int ro4 = (8 * s + lr + 4) * 136;
            #pragma unroll
            for (int n = 0; n < 16; ++n) {
                uint32_t bh0 = INH[ro + 8 * n + lq];
                uint32_t bh1 = INH[ro4 + 8 * n + lq];
                uint32_t bl0 = INL[ro + 8 * n + lq];
                uint32_t bl1 = INL[ro4 + 8 * n + lq];
                mma16(cv[0][n], ah[0], bh0, bh1);
                mma16(cv[1][n], ah[1], bh0, bh1);
                mma16(cv[0][n], al[0], bh0, bh1);
                mma16(cv[1][n], al[1], bh0, bh1);
                mma16(cv[0][n], ah[0], bl0, bl1);
                mma16(cv[1][n], ah[1], bl0, bl1);
            }
        }
    }

    // epilogue: +bias, fp16 pack, store vT [cc][px]
    uint32_t* ov = (uint32_t*)g_vh;
    #pragma unroll
    for (int mm = 0; mm < 2; ++mm) {
        int ccr = m0 + mm * 16 + lq;
        float b0 = __ldg(&bv[ccr]), b8 = __ldg(&bv[ccr + 8]);
        size_t r0 = ((size_t)(b * CC + ccr) * NN + px0) >> 1;
        size_t r8 = r0 + 8 * (NN / 2);
        #pragma unroll
        for (int n = 0; n < 16; ++n) {
            ov[r0 + 4 * n + lr] = pk2(cv[mm][n][0] + b0, cv[mm][n][1] + b0);
            ov[r8 + 4 * n + lr] = pk2(cv[mm][n][2] + b8, cv[mm][n][3] + b8);
        }
    }
}

// ---------------------------------------------------------------------------
// A: fp16 mma flash attention with online softmax (UNCHANGED from R7, passing)
// ---------------------------------------------------------------------------
#define SQH 0
#define SQL 10240
#define SKB 20480
#define SVB 40960
#define SPS 114688
#define SLS 131072
#define SM_AT 133120

__device__ __forceinline__ void load_kv_tile(uint32_t smb, const __half* kh,
                                             const __half* kl, const __half* vh,
                                             int j0, int buf, int t)
{
    if (t < 256) {
        int row = t >> 2, seg = t & 3;
        cp16(smb + SKB + buf * 10240 + row * 80 + seg * 16,
             kh + (size_t)(j0 + row) * DD + seg * 8);
    } else {
        int t2 = t - 256;
        int row = t2 >> 2, seg = t2 & 3;
        cp16(smb + SKB + buf * 10240 + 5120 + row * 80 + seg * 16,
             kl + (size_t)(j0 + row) * DD + seg * 8);
    }
    #pragma unroll
    for (int i = 0; i < 4; ++i) {
        int idx = i * 512 + t;
        int c = idx >> 3, seg = idx & 7;
        cp16(smb + SVB + buf * 36864 + c * 144 + seg * 16,
             vh + (size_t)c * NN + j0 + seg * 8);
    }
}

__global__ void __launch_bounds__(512, 1)
attn_mma_kernel(const float* __restrict__ sem, const float* __restrict__ gammaP,
                float* __restrict__ out)
{
    extern __shared__ char smc[];
    const uint32_t smb = s2u(smc);
    float* red = (float*)(smc + SLS);

    const int t    = threadIdx.x;
    const int lane = t & 31;
    const int wid  = t >> 5;
    const int wm   = wid & 3;
    const int wn   = wid >> 2;
    const int R0   = wm * 32;
    const int J0   = wn * 16;
    const int C0w  = wn * 64;
    const int lq   = lane >> 2;
    const int lr   = lane & 3;

    const int b  = blockIdx.x >> 5;
    const int i0 = (blockIdx.x & 31) << 7;

    const __half* khb = g_kh + (size_t)b * NN * DD;
    const __half* klb = g_kl + (size_t)b * NN * DD;
    const __half* vhb = g_vh + (size_t)b * CC * NN;

    #pragma unroll
    for (int i = 0; i < 2; ++i) {
        int idx = i * 512 + t;
        int row = (idx >> 2) & 127, seg = idx & 3;
        const __half* src = (idx < 512 ? g_qh : g_ql) +
                            ((size_t)(b * NN + i0 + row)) * DD + seg * 8;
        cp16(smb + (idx < 512 ? SQH : SQL) + row * 80 + seg * 16, src);
    }
    load_kv_tile(smb, khb, klb, vhb, 0, 0, t);
    cp_commit();
    cp_wait0();
    __syncthreads();

    float oacc[2][8][4];
    #pragma unroll
    for (int m = 0; m < 2; ++m)
        #pragma unroll
        for (int n = 0; n < 8; ++n)
            #pragma unroll
            for (int k = 0; k < 4; ++k) oacc[m][n][k] = 0.f;
    float lsum[4] = {0.f, 0.f, 0.f, 0.f};
    float mrun[4] = {-1e30f, -1e30f, -1e30f, -1e30f};

    for (int kt = 0; kt < NKT; ++kt) {
        const int buf = kt & 1;
        if (kt + 1 < NKT) {
            load_kv_tile(smb, khb, klb, vhb, (kt + 1) * KT, buf ^ 1, t);
            cp_commit();
        }

        const char* Kh = smc + SKB + buf * 10240;
        const char* Kl = Kh + 5120;
        float sacc[2][2][4];
        #pragma unroll
        for (int m = 0; m < 2; ++m)
            #pragma unroll
            for (int n = 0; n < 2; ++n)
                #pragma unroll
                for (int k = 0; k < 4; ++k) sacc[m][n][k] = 0.f;

        #pragma unroll
        for (int s = 0; s < 2; ++s) {
            uint32_t qh[2][4], ql[2][4];
            const int d = 16 * s + 2 * lr;
            #pragma unroll
            for (int m = 0; m < 2; ++m) {
                int r = R0 + 16 * m + lq;
                qh[m][0] = *(const uint32_t*)(smc + SQH + (r * 40 + d) * 2);
                qh[m][1] = *(const uint32_t*)(smc + SQH + ((r + 8) * 40 + d) * 2);
                qh[m][2] = *(const uint32_t*)(smc + SQH + (r * 40 + d + 8) * 2);
                qh[m][3] = *(const uint32_t*)(smc + SQH + ((r + 8) * 40 + d + 8) * 2);
                ql[m][0] = *(const uint32_t*)(smc + SQL + (r * 40 + d) * 2);
                ql[m][1] = *(const uint32_t*)(smc + SQL + ((r + 8) * 40 + d) * 2);
                ql[m][2] = *(const uint32_t*)(smc + SQL + (r * 40 + d + 8) * 2);
                ql[m][3] = *(const uint32_t*)(smc + SQL + ((r + 8) * 40 + d + 8) * 2);
            }
            #pragma unroll
            for (int n = 0; n < 2; ++n) {
                int j = J0 + 8 * n + lq;
                uint32_t kh0 = *(const uint32_t*)(Kh + (j * 40 + d) * 2);
                uint32_t kh1 = *(const uint32_t*)(Kh + (j * 40 + d + 8) * 2);
                uint32_t kl0 = *(const uint32_t*)(Kl + (j * 40 + d) * 2);
                uint32_t kl1 = *(const uint32_t*)(Kl + (j * 40 + d + 8) * 2);
                mma16(sacc[0][n], qh[0], kh0, kh1);
                mma16(sacc[1][n], qh[1], kh0, kh1);
                mma16(sacc[0][n], ql[0], kh0, kh1);
                mma16(sacc[1][n], ql[1], kh0, kh1);
                mma16(sacc[0][n], qh[0], kl0, kl1);
                mma16(sacc[1][n], qh[1], kl0, kl1);
            }
        }

        float smax[4];
        #pragma unroll
        for (int m = 0; m < 2; ++m) {
            smax[2 * m] = fmaxf(fmaxf(sacc[m][0][0], sacc[m][0][1]),
                                fmaxf(sacc[m][1][0], sacc[m][1][1]));
            smax[2 * m + 1] = fmaxf(fmaxf(sacc[m][0][2], sacc[m][0][3]),
                                    fmaxf(sacc[m][1][2], sacc[m][1][3]));
        }
        #pragma unroll
        for (int i = 0; i < 4; ++i) {
            smax[i] = fmaxf(smax[i], __shfl_xor_sync(0xFFFFFFFFu, smax[i], 1));
            smax[i] = fmaxf(smax[i], __shfl_xor_sync(0xFFFFFFFFu, smax[i], 2));
        }
        if (lr == 0) {
            #pragma unroll
            for (int i = 0; i < 4; ++i)
                red[wn * 128 + R0 + 8 * i + lq] = smax[i];
        }
        __syncthreads();

        float f[4];
        #pragma unroll
        for (int i = 0; i < 4; ++i) {
            int r = R0 + 8 * i + lq;
            float mt = fmaxf(fmaxf(red[r], red[128 + r]),
                             fmaxf(red[256 + r], red[384 + r]));
            float mn = fmaxf(mrun[i], mt);
            f[i] = __expf(mrun[i] - mn);
            mrun[i] = mn;
            lsum[i] *= f[i];
        }
        if (f[0] < 1.f || f[1] < 1.f || f[2] < 1.f || f[3] < 1.f) {
            #pragma unroll
            for (int m = 0; m < 2; ++m)
                #pragma unroll
                for (int n = 0; n < 8; ++n) {
                    oacc[m][n][0] *= f[2 * m];
                    oacc[m][n][1] *= f[2 * m];
                    oacc[m][n][2] *= f[2 * m + 1];
                    oacc[m][n][3] *= f[2 * m + 1];
                }
        }

        #pragma unroll
        for (int m = 0; m < 2; ++m) {
            int r = R0 + 16 * m + lq;
            #pragma unroll
            for (int n = 0; n < 2; ++n) {
                int jp = (J0 + 8 * n) / 2 + lr;
                float p0 = __expf(sacc[m][n][0] - mrun[2 * m]);
                float p1 = __expf(sacc[m][n][1] - mrun[2 * m]);
                float p2 = __expf(sacc[m][n][2] - mrun[2 * m + 1]);
                float p3 = __expf(sacc[m][n][3] - mrun[2 * m + 1]);
                lsum[2 * m]     += p0 + p1;
                lsum[2 * m + 1] += p2 + p3;
                *(uint32_t*)(smc + SPS + (r * 32 + (jp ^ (lq << 2))) * 4) = pk2(p0, p1);
                *(uint32_t*)(smc + SPS + ((r + 8) * 32 + (jp ^ (lq << 2))) * 4) = pk2(p2, p3);
            }
        }
        __syncthreads();

        const char* Vb = smc + SVB + buf * 36864;
        #pragma unroll
        for (int kk = 0; kk < 4; ++kk) {
            uint32_t pa[2][4];
            #pragma unroll
            for (int m = 0; m < 2; ++m) {
                int r = R0 + 16 * m + lq;
                int jp0 = 8 * kk + lr;
                int jp1 = jp0 + 4;
                pa[m][0] = *(const uint32_t*)(smc + SPS + (r * 32 + (jp0 ^ (lq << 2))) * 4);
                pa[m][1] = *(const uint32_t*)(smc + SPS + ((r + 8) * 32 + (jp0 ^ (lq << 2))) * 4);
                pa[m][2] = *(const uint32_t*)(smc + SPS + (r * 32 + (jp1 ^ (lq << 2))) * 4);
                pa[m][3] = *(const uint32_t*)(smc + SPS + ((r + 8) * 32 + (jp1 ^ (lq << 2))) * 4);
            }
            const int d = 16 * kk + 2 * lr;
            #pragma unroll
            for (int n = 0; n < 8; ++n) {
                int c = C0w + 8 * n + lq;
                uint32_t vb0 = *(const uint32_t*)(Vb + (c * 72 + d) * 2);
                uint32_t vb1 = *(const uint32_t*)(Vb + (c * 72 + d + 8) * 2);
                mma16(oacc[0][n], pa[0], vb0, vb1);
                mma16(oacc[1][n], pa[1], vb0, vb1);
            }
        }
        if (kt + 1 < NKT) cp_wait0();
        __syncthreads();
    }

    #pragma unroll
    for (int i = 0; i < 4; ++i) {
        lsum[i] += __shfl_xor_sync(0xFFFFFFFFu, lsum[i], 1);
        lsum[i] += __shfl_xor_sync(0xFFFFFFFFu, lsum[i], 2);
    }
    if (lr == 0) {
        #pragma unroll
        for (int i = 0; i < 4; ++i)
            red[wn * 128 + R0 + 8 * i + lq] = lsum[i];
    }
    __syncthreads();

    float linv[4];
    #pragma unroll
    for (int i = 0; i < 4; ++i) {
        int r = R0 + 8 * i + lq;
        linv[i] = 1.f / (red[r] + red[128 + r] + red[256 + r] + red[384 + r]);
    }

    const float g = gammaP[0];
    #pragma unroll
    for (int m = 0; m < 2; ++m) {
        #pragma unroll
        for (int n = 0; n < 8; ++n) {
            int ch = C0w + 8 * n + 2 * lr;
            size_t ia = ((size_t)(b * CC + ch)) * NN + i0 + R0 + 16 * m + lq;
            out[ia]          = g * oacc[m][n][0] * linv[2 * m]     + sem[ia];
            out[ia + NN]     = g * oacc[m][n][1] * linv[2 * m]     + sem[ia + NN];
            out[ia + 8]      = g * oacc[m][n][2] * linv[2 * m + 1] + sem[ia + 8];
            out[ia + NN + 8] = g * oacc[m][n][3] * linv[2 * m + 1] + sem[ia + NN + 8];
        }
    }
}

// ---------------------------------------------------------------------------
extern "C" void kernel_launch(void* const* d_in, const int* in_sizes, int n_in,
                              void* d_out, int out_size)
{
    const float* sem = (const float*)d_in[0];
    const float* str = (const float*)d_in[1];
    const float* Wq  = (const float*)d_in[2];
    const float* bq  = (const float*)d_in[3];
    const float* Wk  = (const float*)d_in[4];
    const float* bk  = (const float*)d_in[5];
    const float* Wv  = (const float*)d_in[6];
    const float* bv  = (const float*)d_in[7];
    const float* gam = (const float*)d_in[8];
    float* out = (float*)d_out;

    const int smem_p1 = P1_TOT * 4;   // 68608
    const int smem_p2 = P2_TOT * 4;   // 108544
    const int smem_at = SM_AT;        // 133120

    cudaFuncSetAttribute(proj_qk_mma,
        cudaFuncAttributeMaxDynamicSharedMemorySize, smem_p1);
    cudaFuncSetAttribute(proj_v_mma,
        cudaFuncAttributeMaxDynamicSharedMemorySize, smem_p2);
    cudaFuncSetAttribute(attn_mma_kernel,
        cudaFuncAttributeMaxDynamicSharedMemorySize, smem_at);

    proj_qk_mma<<<BB * (NN / 128), 256, smem_p1>>>(sem, str, Wq, bq, Wk, bk);
    proj_v_mma<<<BB * (NN / 128), 256, smem_p2>>>(str, Wv, bv);
    attn_mma_kernel<<<BB * (NN / 128), 512, smem_at>>>(sem, gam, out);
}